// round 2
// baseline (speedup 1.0000x reference)
#include <cuda_runtime.h>

// Problem constants (shapes fixed by the dataset)
#define BATCH 64
#define FT    51200            // 80 * 640
#define BFT   3276800          // 64 * 80 * 640 (per-channel flattened length)
#define NAUX  32
#define WPB   1600             // FT / 32 bitset words per batch
#define THRESH 20.0f

// Scratch: strain peak bitset (bit j of word (b*WPB + j/32) = peak at in-batch
// flat index j) + per-batch strain peak counts. __device__ globals (no allocs).
__device__ unsigned g_sbits[BATCH * WPB];
__device__ int g_c1[BATCH];

__device__ __forceinline__ float finf() { return __int_as_float(0x7f800000); }

// Reduce v over the block; result valid in thread 0. sh must hold >= NT/32 ints.
template <int NT>
__device__ __forceinline__ int block_reduce(int v, int* sh) {
#pragma unroll
    for (int o = 16; o > 0; o >>= 1) v += __shfl_down_sync(0xffffffffu, v, o);
    const int wid = threadIdx.x >> 5;
    if ((threadIdx.x & 31) == 0) sh[wid] = v;
    __syncthreads();
    v = 0;
    if (threadIdx.x < (NT / 32)) v = sh[threadIdx.x];
    if (threadIdx.x < 32) {
#pragma unroll
        for (int o = 16; o > 0; o >>= 1) v += __shfl_down_sync(0xffffffffu, v, o);
    }
    return v;
}

// Compute the 4-bit peak nibble for a float4 given its outer neighbors.
// Equivalent to reference clamp(0)+strict-local-max+height>=20 because
// THRESH > 0 makes the clamp a no-op on the peak condition.
__device__ __forceinline__ unsigned peak_nibble(float4 v, float left, float right) {
    unsigned p0 = (v.x > fmaxf(left, v.y)) && (v.x >= THRESH);
    unsigned p1 = (v.y > fmaxf(v.x, v.z)) && (v.y >= THRESH);
    unsigned p2 = (v.z > fmaxf(v.y, v.w)) && (v.z >= THRESH);
    unsigned p3 = (v.w > fmaxf(v.z, right)) && (v.w >= THRESH);
    return p0 | (p1 << 1) | (p2 << 2) | (p3 << 3);
}

// ---------------------------------------------------------------------------
// Kernel A: strain peak bitset + per-batch counts. One block per batch b.
// Peaks are over the FULL flattened [B,F,T] array, so neighbors cross batch
// boundaries (valid reads within the strain buffer); only global indices 0 and
// BFT-1 are excluded (INF sentinel kills the strict > test).
// ---------------------------------------------------------------------------
__global__ __launch_bounds__(1024) void strain_kernel(const float* __restrict__ s) {
    const int b = blockIdx.x;
    const int tid = threadIdx.x;
    const int lane = tid & 31;
    const int bFT = b * FT;
    const float4* s4 = reinterpret_cast<const float4*>(s + (size_t)bFT);
    int cnt = 0;

    for (int q = tid; q < FT / 4; q += 1024) {   // FT/4 = 12800; last iter = 512 thr (full warps)
        float4 v = s4[q];
        float left  = __shfl_up_sync(0xffffffffu, v.w, 1);
        float right = __shfl_down_sync(0xffffffffu, v.x, 1);
        const int j = q << 2;
        if (lane == 0)  left  = (bFT + j == 0)       ? finf() : __ldg(s + bFT + j - 1);
        if (lane == 31) right = (bFT + j + 4 == BFT) ? finf() : __ldg(s + bFT + j + 4);

        unsigned nib = peak_nibble(v, left, right);
        cnt += __popc(nib);

        // Assemble 32-bit words across groups of 8 lanes (4 bits each).
        unsigned sh = nib << ((lane & 7) << 2);
        sh |= __shfl_xor_sync(0xffffffffu, sh, 1);
        sh |= __shfl_xor_sync(0xffffffffu, sh, 2);
        sh |= __shfl_xor_sync(0xffffffffu, sh, 4);
        if ((lane & 7) == 0) g_sbits[b * WPB + (q >> 3)] = sh;
    }

    __shared__ int smem[32];
    int tot = block_reduce<1024>(cnt, smem);
    if (tid == 0) g_c1[b] = tot;
}

// ---------------------------------------------------------------------------
// Kernel B: per (n, b) block — stream the 51200-element slab, build peak
// nibbles, AND with the strain bitset (L2-resident: 410 KB total), popcount,
// block-reduce, and emit jaccard + intersection/|strain| directly.
// ---------------------------------------------------------------------------
__global__ __launch_bounds__(512) void aux_kernel(const float* __restrict__ aux,
                                                  float* __restrict__ out,
                                                  int half) {
    const int b = blockIdx.x;     // 0..63
    const int n = blockIdx.y;     // 0..31
    const int tid = threadIdx.x;
    const int lane = tid & 31;

    const float* ch = aux + (size_t)n * BFT;             // channel base (peaks flatten per channel)
    const int bFT = b * FT;
    const float4* c4 = reinterpret_cast<const float4*>(ch + (size_t)bFT);
    const unsigned* __restrict__ sb = g_sbits + b * WPB;

    int inter = 0, c2 = 0;

#pragma unroll 5
    for (int it = 0; it < 25; ++it) {                    // 25 * 512 = 12800 float4s
        const int q = it * 512 + tid;
        float4 v = c4[q];
        float left  = __shfl_up_sync(0xffffffffu, v.w, 1);
        float right = __shfl_down_sync(0xffffffffu, v.x, 1);
        const int j = q << 2;
        if (lane == 0)  left  = (bFT + j == 0)       ? finf() : __ldg(ch + bFT + j - 1);
        if (lane == 31) right = (bFT + j + 4 == BFT) ? finf() : __ldg(ch + bFT + j + 4);

        unsigned nib = peak_nibble(v, left, right);
        unsigned sw = sb[q >> 3];                        // 8 lanes broadcast same word
        inter += __popc((sw >> ((q & 7) << 2)) & nib);
        c2 += __popc(nib);
    }

    __shared__ int smem[16];
    int ti = block_reduce<512>(inter, smem);
    __syncthreads();
    int tc = block_reduce<512>(c2, smem);

    if (tid == 0) {
        const int c1 = g_c1[b];
        const int uni = c1 + tc - ti;                    // uni == 0 implies ti == 0
        float jac, ratio;
        if (uni == 0) {
            jac = 1.0f; ratio = 1.0f;                    // empty-vs-empty convention
        } else {
            jac = (float)ti / (float)uni;
            ratio = (c1 == 0) ? 0.0f : (float)ti / (float)c1;  // nan_to_num(0/0) -> 0
        }
        const int idx = n * BATCH + b;
        out[idx] = jac;
        out[half + idx] = ratio;
    }
}

extern "C" void kernel_launch(void* const* d_in, const int* in_sizes, int n_in,
                              void* d_out, int out_size) {
    // metadata order: qt_strain [64,80,640], qt_aux [32,64,80,640]; guard by size.
    const float* strain = (const float*)d_in[0];
    const float* aux    = (const float*)d_in[1];
    if (n_in >= 2 && in_sizes[0] != BFT) {   // defensive: swap if order differs
        strain = (const float*)d_in[1];
        aux    = (const float*)d_in[0];
    }
    float* out = (float*)d_out;

    strain_kernel<<<BATCH, 1024>>>(strain);
    dim3 grid(BATCH, NAUX);
    aux_kernel<<<grid, 512>>>(aux, out, out_size >> 1);
}

// round 3
// speedup vs baseline: 1.3125x; 1.3125x over previous
#include <cuda_runtime.h>

// Problem constants (shapes fixed by the dataset)
#define BATCH 64
#define FT    51200            // 80 * 640 elements per (channel,batch) slab
#define BFT   3276800          // 64*80*640 per-channel flattened length
#define NAUX  32
#define WPB   1600             // FT/32 bitset words per batch
#define NPAIR 2048             // NAUX * BATCH
#define NFIFTH 5
#define F4_PER_FIFTH 2560      // 12800/5
#define F4_PER_WARP 320        // 2560/8 warps
#define FULLM 0xffffffffu

// Largest float strictly below 20.0f: (x > TH_LT) <=> (x >= 20.0f)
#define TH_LT __int_as_float(0x419FFFFF)

// Scratch (__device__ globals — no allocations). All fully overwritten each
// launch -> deterministic across graph replays.
__device__ unsigned g_sbits[BATCH * WPB];
__device__ int g_pi[NPAIR * NFIFTH];   // partial intersections
__device__ int g_pc[NPAIR * NFIFTH];   // partial aux peak counts
__device__ int g_pa[NPAIR * NFIFTH];   // partial 8*c1 accumulators

__device__ __forceinline__ float finf() { return __int_as_float(0x7f800000); }

// One predicate per element (2 FMNMX + FSETP), SEL with pre-shifted immediate,
// 2 LOP3 to assemble the nibble.
__device__ __forceinline__ unsigned nib4(float4 v, float l, float r) {
    unsigned b0 = (v.x > fmaxf(fmaxf(l,   v.y), TH_LT)) ? 1u : 0u;
    unsigned b1 = (v.y > fmaxf(fmaxf(v.x, v.z), TH_LT)) ? 2u : 0u;
    unsigned b2 = (v.z > fmaxf(fmaxf(v.y, v.w), TH_LT)) ? 4u : 0u;
    unsigned b3 = (v.w > fmaxf(fmaxf(v.z, r),   TH_LT)) ? 8u : 0u;
    return (b0 | b1) | (b2 | b3);
}

// ---------------------------------------------------------------------------
// Strain kernel: build the peak bitset. Grid = 64*5 blocks, 256 threads.
// Each warp owns a contiguous 320-float4 (1280-element) run; neighbor exchange
// via shuffles with a register carry across iterations; exactly 2 scalar
// boundary loads per warp, hoisted.
// ---------------------------------------------------------------------------
__global__ __launch_bounds__(256, 4) void strain_kernel(const float* __restrict__ s) {
    const int blk = blockIdx.x;
    const int b = blk / NFIFTH, fifth = blk - b * NFIFTH;
    const int tid = threadIdx.x, lane = tid & 31, w = tid >> 5;

    const int slab4 = fifth * F4_PER_FIFTH + w * F4_PER_WARP;  // float4 idx in slab
    const int gelem = b * FT + slab4 * 4;                      // element idx in buffer
    const float4* p4 = reinterpret_cast<const float4*>(s + gelem);
    unsigned* wp = g_sbits + b * WPB + (slab4 >> 3) + (lane >> 3);
    const int sh = (lane & 7) << 2;

    float carry = (gelem == 0) ? finf() : __ldg(s + gelem - 1);
    const float rlast = (gelem + 4 * F4_PER_WARP == BFT) ? finf()
                                                         : __ldg(s + gelem + 4 * F4_PER_WARP);
    float4 v = p4[lane];
#pragma unroll
    for (int it = 0; it < 10; ++it) {
        float4 vn = v;
        if (it < 9) vn = p4[(it + 1) * 32 + lane];
        float l = __shfl_up_sync(FULLM, v.w, 1);
        if (lane == 0) l = carry;
        float r = __shfl_down_sync(FULLM, v.x, 1);
        float r31 = (it < 9) ? __shfl_sync(FULLM, vn.x, 0) : rlast;
        if (lane == 31) r = r31;
        carry = __shfl_sync(FULLM, v.w, 31);

        unsigned word = nib4(v, l, r) << sh;
        word |= __shfl_xor_sync(FULLM, word, 1);
        word |= __shfl_xor_sync(FULLM, word, 2);
        word |= __shfl_xor_sync(FULLM, word, 4);
        if ((lane & 7) == 0) wp[it * 4] = word;
        v = vn;
    }
}

// ---------------------------------------------------------------------------
// Aux kernel: grid = 2048 pairs * 5 fifths = 10240 blocks, 256 threads.
// Streams 10240 elements/block, ANDs peak nibbles against the L2-resident
// strain bitset, writes 3 int partials (no atomics).
// ---------------------------------------------------------------------------
__global__ __launch_bounds__(256, 4) void aux_kernel(const float* __restrict__ aux) {
    const int blk = blockIdx.x;
    const int pair = blk / NFIFTH, fifth = blk - pair * NFIFTH;
    const int b = pair & 63, n = pair >> 6;
    const int tid = threadIdx.x, lane = tid & 31, w = tid >> 5;

    const float* ch = aux + (size_t)n * BFT;
    const int slab4 = fifth * F4_PER_FIFTH + w * F4_PER_WARP;
    const int gelem = b * FT + slab4 * 4;
    const float4* p4 = reinterpret_cast<const float4*>(ch + gelem);
    const unsigned* __restrict__ swp = g_sbits + b * WPB + (slab4 >> 3) + (lane >> 3);
    const int sh = (lane & 7) << 2;

    float carry = (gelem == 0) ? finf() : __ldg(ch + gelem - 1);
    const float rlast = (gelem + 4 * F4_PER_WARP == BFT) ? finf()
                                                         : __ldg(ch + gelem + 4 * F4_PER_WARP);
    int inter = 0, c2 = 0, c1a = 0;
    float4 v = p4[lane];
#pragma unroll
    for (int it = 0; it < 10; ++it) {
        float4 vn = v;
        if (it < 9) vn = p4[(it + 1) * 32 + lane];
        float l = __shfl_up_sync(FULLM, v.w, 1);
        if (lane == 0) l = carry;
        float r = __shfl_down_sync(FULLM, v.x, 1);
        float r31 = (it < 9) ? __shfl_sync(FULLM, vn.x, 0) : rlast;
        if (lane == 31) r = r31;
        carry = __shfl_sync(FULLM, v.w, 31);

        unsigned nib = nib4(v, l, r);
        unsigned sw = __ldg(swp + it * 4);            // 8 lanes broadcast same word
        inter += __popc((sw >> sh) & nib);
        c2 += __popc(nib);
        c1a += __popc(sw);                            // sums to 8*c1 over the slab
        v = vn;
    }

    // Block reduce 3 ints (8 warps).
    __shared__ int sm0[8], sm1[8], sm2[8];
#pragma unroll
    for (int o = 16; o > 0; o >>= 1) {
        inter += __shfl_down_sync(FULLM, inter, o);
        c2    += __shfl_down_sync(FULLM, c2, o);
        c1a   += __shfl_down_sync(FULLM, c1a, o);
    }
    if (lane == 0) { sm0[w] = inter; sm1[w] = c2; sm2[w] = c1a; }
    __syncthreads();
    if (tid == 0) {
        int a = 0, bb = 0, c = 0;
#pragma unroll
        for (int k = 0; k < 8; ++k) { a += sm0[k]; bb += sm1[k]; c += sm2[k]; }
        g_pi[blk] = a; g_pc[blk] = bb; g_pa[blk] = c;
    }
}

// ---------------------------------------------------------------------------
// Finalize: 2048 threads; sum 5 partials each, emit jaccard + ratio.
// ---------------------------------------------------------------------------
__global__ void fin_kernel(float* __restrict__ out, int half) {
    const int idx = blockIdx.x * blockDim.x + threadIdx.x;
    if (idx >= NPAIR) return;
    int ti = 0, tc = 0, ta = 0;
#pragma unroll
    for (int k = 0; k < NFIFTH; ++k) {
        ti += g_pi[idx * NFIFTH + k];
        tc += g_pc[idx * NFIFTH + k];
        ta += g_pa[idx * NFIFTH + k];
    }
    const int c1 = ta >> 3;
    const int uni = c1 + tc - ti;
    float jac, ratio;
    if (uni == 0) {
        jac = 1.0f; ratio = 1.0f;                     // empty-vs-empty
    } else {
        jac = (float)ti / (float)uni;
        ratio = (c1 == 0) ? 0.0f : (float)ti / (float)c1;  // nan_to_num(0/0)->0
    }
    out[idx] = jac;
    out[half + idx] = ratio;
}

extern "C" void kernel_launch(void* const* d_in, const int* in_sizes, int n_in,
                              void* d_out, int out_size) {
    const float* strain = (const float*)d_in[0];
    const float* aux    = (const float*)d_in[1];
    if (n_in >= 2 && in_sizes[0] != BFT) {            // defensive order check
        strain = (const float*)d_in[1];
        aux    = (const float*)d_in[0];
    }
    float* out = (float*)d_out;

    strain_kernel<<<BATCH * NFIFTH, 256>>>(strain);
    aux_kernel<<<NPAIR * NFIFTH, 256>>>(aux);
    fin_kernel<<<2, 1024>>>(out, out_size >> 1);
}

// round 4
// speedup vs baseline: 1.4311x; 1.0904x over previous
#include <cuda_runtime.h>

// Problem constants (shapes fixed by the dataset)
#define BATCH 64
#define FT    51200            // 80 * 640 elements per (channel,batch) slab
#define BFT   3276800          // 64*80*640 per-channel flattened length
#define NAUX  32
#define WPB   1600             // FT/32 bitset words per batch
#define NPAIR 2048             // NAUX * BATCH
#define NFIFTH 5               // aux slab split
#define F4_PER_FIFTH 2560      // 12800/5
#define AUX_F4_PER_WARP 320    // 2560/8 warps
#define NSEG 25                // strain slab split (finer: latency-bound kernel)
#define F4_PER_SEG 512         // 12800/25
#define STR_F4_PER_WARP 64     // 512/8 warps -> 2 iterations
#define FULLM 0xffffffffu

// Largest float strictly below 20.0f: (x > TH_LT) <=> (x >= 20.0f)
#define TH_LT __int_as_float(0x419FFFFF)

// Scratch (__device__ globals — no allocations). All fully overwritten each
// launch -> deterministic across graph replays.
__device__ unsigned g_sbits[BATCH * WPB];
__device__ int g_pi[NPAIR * NFIFTH];   // partial intersections
__device__ int g_pc[NPAIR * NFIFTH];   // partial aux peak counts
__device__ int g_pa[NPAIR * NFIFTH];   // partial 8*c1 accumulators

__device__ __forceinline__ float finf() { return __int_as_float(0x7f800000); }

// One predicate per element (2 FMNMX + FSETP), SEL with pre-shifted immediate,
// LOP3s to assemble the nibble.
__device__ __forceinline__ unsigned nib4(float4 v, float l, float r) {
    unsigned b0 = (v.x > fmaxf(fmaxf(l,   v.y), TH_LT)) ? 1u : 0u;
    unsigned b1 = (v.y > fmaxf(fmaxf(v.x, v.z), TH_LT)) ? 2u : 0u;
    unsigned b2 = (v.z > fmaxf(fmaxf(v.y, v.w), TH_LT)) ? 4u : 0u;
    unsigned b3 = (v.w > fmaxf(fmaxf(v.z, r),   TH_LT)) ? 8u : 0u;
    return (b0 | b1) | (b2 | b3);
}

// ---------------------------------------------------------------------------
// Strain kernel: build the peak bitset. Grid = 64*25 = 1600 blocks, 256 thr.
// Each warp owns 64 contiguous float4s (2 iterations) — short dependency
// chains + high occupancy (R3 showed the 10-iter version latency-bound at
// occ=23%, DRAM=16%).
// ---------------------------------------------------------------------------
__global__ __launch_bounds__(256, 4) void strain_kernel(const float* __restrict__ s) {
    const int blk = blockIdx.x;
    const int b = blk / NSEG, seg = blk - b * NSEG;
    const int tid = threadIdx.x, lane = tid & 31, w = tid >> 5;

    const int slab4 = seg * F4_PER_SEG + w * STR_F4_PER_WARP;  // float4 idx in slab
    const int gelem = b * FT + slab4 * 4;                      // element idx in buffer
    const float4* p4 = reinterpret_cast<const float4*>(s + gelem);
    unsigned* wp = g_sbits + b * WPB + (slab4 >> 3) + (lane >> 3);
    const int sh = (lane & 7) << 2;

    float carry = (gelem == 0) ? finf() : __ldg(s + gelem - 1);
    const float rlast = (gelem + 4 * STR_F4_PER_WARP == BFT)
                            ? finf()
                            : __ldg(s + gelem + 4 * STR_F4_PER_WARP);
    float4 v = p4[lane];
#pragma unroll
    for (int it = 0; it < 2; ++it) {
        float4 vn = v;
        if (it < 1) vn = p4[32 + lane];
        float l = __shfl_up_sync(FULLM, v.w, 1);
        if (lane == 0) l = carry;
        float r = __shfl_down_sync(FULLM, v.x, 1);
        float r31 = (it < 1) ? __shfl_sync(FULLM, vn.x, 0) : rlast;
        if (lane == 31) r = r31;
        carry = __shfl_sync(FULLM, v.w, 31);

        unsigned word = nib4(v, l, r) << sh;
        word |= __shfl_xor_sync(FULLM, word, 1);
        word |= __shfl_xor_sync(FULLM, word, 2);
        word |= __shfl_xor_sync(FULLM, word, 4);
        if ((lane & 7) == 0) wp[it * 4] = word;
        v = vn;
    }
}

// ---------------------------------------------------------------------------
// Aux kernel: grid = 2048 pairs * 5 fifths = 10240 blocks, 256 threads.
// Streams 10240 elements/block (evict-first: data touched exactly once),
// ANDs peak nibbles against the L2-resident strain bitset, writes 3 int
// partials (no atomics).
// ---------------------------------------------------------------------------
__global__ __launch_bounds__(256, 4) void aux_kernel(const float* __restrict__ aux) {
    const int blk = blockIdx.x;
    const int pair = blk / NFIFTH, fifth = blk - pair * NFIFTH;
    const int b = pair & 63, n = pair >> 6;
    const int tid = threadIdx.x, lane = tid & 31, w = tid >> 5;

    const float* ch = aux + (size_t)n * BFT;
    const int slab4 = fifth * F4_PER_FIFTH + w * AUX_F4_PER_WARP;
    const int gelem = b * FT + slab4 * 4;
    const float4* p4 = reinterpret_cast<const float4*>(ch + gelem);
    const unsigned* __restrict__ swp = g_sbits + b * WPB + (slab4 >> 3) + (lane >> 3);
    const int sh = (lane & 7) << 2;

    float carry = (gelem == 0) ? finf() : __ldg(ch + gelem - 1);
    const float rlast = (gelem + 4 * AUX_F4_PER_WARP == BFT)
                            ? finf()
                            : __ldg(ch + gelem + 4 * AUX_F4_PER_WARP);
    int inter = 0, c2 = 0, c1a = 0;
    float4 v = __ldcs(&p4[lane]);
#pragma unroll
    for (int it = 0; it < 10; ++it) {
        float4 vn = v;
        if (it < 9) vn = __ldcs(&p4[(it + 1) * 32 + lane]);
        float l = __shfl_up_sync(FULLM, v.w, 1);
        if (lane == 0) l = carry;
        float r = __shfl_down_sync(FULLM, v.x, 1);
        float r31 = (it < 9) ? __shfl_sync(FULLM, vn.x, 0) : rlast;
        if (lane == 31) r = r31;
        carry = __shfl_sync(FULLM, v.w, 31);

        unsigned nib = nib4(v, l, r);
        unsigned sw = __ldg(swp + it * 4);            // 8 lanes broadcast same word
        inter += __popc((sw >> sh) & nib);
        c2 += __popc(nib);
        c1a += __popc(sw);                            // sums to 8*c1 over the slab
        v = vn;
    }

    // Block reduce 3 ints (8 warps).
    __shared__ int sm0[8], sm1[8], sm2[8];
#pragma unroll
    for (int o = 16; o > 0; o >>= 1) {
        inter += __shfl_down_sync(FULLM, inter, o);
        c2    += __shfl_down_sync(FULLM, c2, o);
        c1a   += __shfl_down_sync(FULLM, c1a, o);
    }
    if (lane == 0) { sm0[w] = inter; sm1[w] = c2; sm2[w] = c1a; }
    __syncthreads();
    if (tid == 0) {
        int a = 0, bb = 0, c = 0;
#pragma unroll
        for (int k = 0; k < 8; ++k) { a += sm0[k]; bb += sm1[k]; c += sm2[k]; }
        g_pi[blk] = a; g_pc[blk] = bb; g_pa[blk] = c;
    }
}

// ---------------------------------------------------------------------------
// Finalize: 2048 threads; sum 5 partials each, emit jaccard + ratio.
// ---------------------------------------------------------------------------
__global__ void fin_kernel(float* __restrict__ out, int half) {
    const int idx = blockIdx.x * blockDim.x + threadIdx.x;
    if (idx >= NPAIR) return;
    int ti = 0, tc = 0, ta = 0;
#pragma unroll
    for (int k = 0; k < NFIFTH; ++k) {
        ti += g_pi[idx * NFIFTH + k];
        tc += g_pc[idx * NFIFTH + k];
        ta += g_pa[idx * NFIFTH + k];
    }
    const int c1 = ta >> 3;
    const int uni = c1 + tc - ti;
    float jac, ratio;
    if (uni == 0) {
        jac = 1.0f; ratio = 1.0f;                     // empty-vs-empty
    } else {
        jac = (float)ti / (float)uni;
        ratio = (c1 == 0) ? 0.0f : (float)ti / (float)c1;  // nan_to_num(0/0)->0
    }
    out[idx] = jac;
    out[half + idx] = ratio;
}

extern "C" void kernel_launch(void* const* d_in, const int* in_sizes, int n_in,
                              void* d_out, int out_size) {
    const float* strain = (const float*)d_in[0];
    const float* aux    = (const float*)d_in[1];
    if (n_in >= 2 && in_sizes[0] != BFT) {            // defensive order check
        strain = (const float*)d_in[1];
        aux    = (const float*)d_in[0];
    }
    float* out = (float*)d_out;

    strain_kernel<<<BATCH * NSEG, 256>>>(strain);
    aux_kernel<<<NPAIR * NFIFTH, 256>>>(aux);
    fin_kernel<<<2, 1024>>>(out, out_size >> 1);
}